// round 16
// baseline (speedup 1.0000x reference)
#include <cuda_runtime.h>
#include <math.h>

#ifndef M_PI
#define M_PI 3.14159265358979323846
#endif

#define NBLK  296          // 2 blocks per SM (148 SMs) — latency hiding
#define NT    448
#define NWARP 14
#define TXDIM 421
#define TYDIM 421
#define NRMAX 2
#define SRCI  210
#define SRCJ  210
#define SRCBUF 256

// Flag+data packets, ring depth 2 (write slot t&1, read slot (t+1)&1):
//  pktT: {ez_row_first, 0, _, seq} — consumed by bid-1 as ezBot
//  pktB: {ez_row_last, hy_row_last, _, seq} — consumed by bid+1 as ezTop/hyTop
__device__ float4   g_pktT[2][NBLK][NT];
__device__ float4   g_pktB[2][NBLK][NT];
__device__ unsigned g_epoch;   // monotonic across graph replays

static __device__ __forceinline__ void st_pkt(float4* p, float x, float y, unsigned seq) {
    asm volatile("st.volatile.global.v4.f32 [%0], {%1,%2,%3,%4};"
                 :: "l"(p), "f"(x), "f"(y), "f"(0.f), "f"(__uint_as_float(seq)) : "memory");
}
static __device__ __forceinline__ float4 ld_pkt(const float4* p) {
    float4 v;
    asm volatile("ld.volatile.global.v4.f32 {%0,%1,%2,%3}, [%4];"
                 : "=f"(v.x), "=f"(v.y), "=f"(v.z), "=f"(v.w) : "l"(p) : "memory");
    return v;
}

__global__ void __launch_bounds__(NT, 2)   // 2 blocks/SM REQUIRED for residency
fdtd_mlor_kernel(const float* __restrict__ src, int src_len,
                 const float* __restrict__ C1a, const float* __restrict__ C2a,
                 const float* __restrict__ Cbdxa, const float* __restrict__ Cbdya,
                 const float* __restrict__ dbhxa, const float* __restrict__ dbhya,
                 const float* __restrict__ Caa, const float* __restrict__ Cba,
                 const float* __restrict__ Cca, const float* __restrict__ Cda,
                 const float* __restrict__ Cea,
                 const float* __restrict__ sig_ex, const float* __restrict__ sig_ey,
                 const float* __restrict__ sig_hx, const float* __restrict__ sig_hy,
                 const int* __restrict__ nsp,
                 float* __restrict__ out,
                 float kE, float kMu)
{
    const int bid  = blockIdx.x;
    const int j    = threadIdx.x;
    const int w    = j >> 5;
    const int lane = j & 31;

    const float ca   = Caa[0], cb = Cba[0], cc = Cca[0], cd = Cda[0], ce = Cea[0];
    const float C1   = C1a[0], C2 = C2a[0];
    const float Cbdx = Cbdxa[0], Cbdy = Cbdya[0];
    const float dbhx = dbhxa[0], dbhy = dbhya[0];

    int n = nsp ? nsp[0] : 200;
    if (n > src_len) n = src_len;
    if (n < 0) n = 0;

    const int r0 = (bid * TXDIM) / NBLK;
    const int r1 = ((bid + 1) * TXDIM) / NBLK;
    const int nrows = r1 - r0;                 // 1 or 2 (block-uniform)
    const bool hasL = (bid > 0);
    const bool hasU = (bid < NBLK - 1);

    const bool colE = (j < TYDIM);
    const bool colH = (j < TYDIM - 1);
    const bool colM = (j >= 1 && j < TYDIM);
    const bool inJ  = (j >= 1 && j <= TYDIM - 2);

    float cEyE = 1.f, cEyMu = 1.f, cHyMu = 1.f, cHyMuM = 1.f;
    if (colE) { float s = sig_ey[j]; cEyE = expf(-s * kE); cEyMu = expf(-s * kMu); }
    if (colH) cHyMu  = expf(-sig_hy[j]     * kMu);
    if (colM) cHyMuM = expf(-sig_hy[j - 1] * kMu);

    // Predicate-folded coefficients: zero ⇒ field stays 0 (reference border mask).
    float fDe[NRMAX], fHx[NRMAX], fHxm[NRMAX], fHy[NRMAX];
    #pragma unroll
    for (int r = 0; r < NRMAX; ++r) {
        fDe[r] = 0.f; fHx[r] = 0.f; fHxm[r] = 0.f; fHy[r] = 0.f;
        if (r < nrows) {
            int i = r0 + r;
            float sx  = sig_ex[i];
            float rMu = expf(-sx * kMu);
            bool  inI = (i >= 1 && i <= TXDIM - 2);
            fDe[r]  = (inI && inJ) ? expf(-sx * kE) * cEyE : 0.f;
            fHx[r]  = colH ? rMu * cHyMu  : 0.f;
            fHxm[r] = colM ? rMu * cHyMuM : 0.f;
            fHy[r]  = (i < TXDIM - 1 && colE) ? expf(-sig_hx[i] * kMu) * cEyMu : 0.f;
        }
    }
    const float fHyHalo = (r0 > 0 && colE) ? expf(-sig_hx[r0 - 1] * kMu) * cEyMu : 0.f;

    // Field state — registers for the whole run
    float ez[NRMAX]   = {0.f, 0.f};
    float eold[NRMAX] = {0.f, 0.f};
    float jz[NRMAX]   = {0.f, 0.f};
    float jold[NRMAX] = {0.f, 0.f};
    float hx[NRMAX]   = {0.f, 0.f};
    float hxm[NRMAX]  = {0.f, 0.f};
    float hy[NRMAX]   = {0.f, 0.f};

    // Warp-edge Ez, double-buffered; read only AFTER the barrier (never spun on).
    __shared__ float sEdgeL[2][NWARP][4];
    __shared__ float sEdgeR[2][NWARP][4];
    __shared__ float sSrc[SRCBUF];

    if (j < 2 * NWARP * 4) { ((float*)sEdgeL)[j] = 0.f; ((float*)sEdgeR)[j] = 0.f; }
    if (j < n && j < SRCBUF) sSrc[j] = src[j];

    const unsigned base = *(volatile unsigned*)&g_epoch;

    // Loop-invariant packet pointers (slots compile-time per unrolled body)
    const int bidm = hasL ? bid - 1 : bid;
    const int bidp = hasU ? bid + 1 : bid;
    const float4* pBr[2] = { &g_pktB[0][bidm][j], &g_pktB[1][bidm][j] };
    const float4* pTr[2] = { &g_pktT[0][bidp][j], &g_pktT[1][bidp][j] };
    float4*       pTw[2] = { &g_pktT[0][bid][j],  &g_pktT[1][bid][j]  };
    float4*       pBw[2] = { &g_pktB[0][bid][j],  &g_pktB[1][bid][j]  };

    const bool srcBlk = (r0 <= SRCI) && (SRCI < r1) && (j == SRCJ);
    const bool s0 = srcBlk && (SRCI - r0 == 0);
    const bool s1 = srcBlk && (SRCI - r0 == 1);

    __syncthreads();   // init visible

#define EUPD(r, hyBelow, sflag)                                                    \
    do {                                                                           \
        float chy_ = hy[(r)] - (hyBelow);                                          \
        float chx_ = hx[(r)] - hxm[(r)];                                           \
        float ezn_ = fDe[(r)] * (C1 * ez[(r)] + Cbdx * chy_ - Cbdy * chx_          \
                                 - C2 * phi[(r)]);                                 \
        if (sflag) ezn_ += sv;                                                     \
        jold[(r)] = jz[(r)]; jz[(r)] = jpart[(r)] + cc * ezn_;                     \
        eold[(r)] = ez[(r)]; ez[(r)] = ezn_;                                       \
    } while (0)

    // One full step. PR/PW = packet read/write slot, ER/EW = edge read/write slot.
#define STEP_BODY(T, PR, PW, ER, EW)                                               \
    do {                                                                           \
        const unsigned want = base + (unsigned)(T);                                \
        const bool nB = ((T) > 0) && hasL;                                         \
        const bool nT = ((T) > 0) && hasU;                                         \
        float4 vB = make_float4(0.f, 0.f, 0.f, 0.f);                               \
        float4 vT = make_float4(0.f, 0.f, 0.f, 0.f);                               \
        if (nB) vB = ld_pkt(pBr[PR]);                                              \
        if (nT) vT = ld_pkt(pTr[PR]);                                              \
        const float sv = sSrc[(T)];                                                \
        /* j±1 exchange: shfl in-warp, shared at warp edges */                     \
        float ezp1[NRMAX], ezm1[NRMAX];                                            \
        _Pragma("unroll")                                                          \
        for (int r = 0; r < NRMAX; ++r) {                                          \
            ezp1[r] = __shfl_down_sync(0xffffffffu, ez[r], 1);                     \
            ezm1[r] = __shfl_up_sync  (0xffffffffu, ez[r], 1);                     \
        }                                                                          \
        if (lane == 31 && w < NWARP - 1) {                                         \
            ezp1[0] = sEdgeL[ER][w + 1][0];                                        \
            ezp1[1] = sEdgeL[ER][w + 1][1];                                        \
        }                                                                          \
        if (lane == 0 && w > 0) {                                                  \
            ezm1[0] = sEdgeR[ER][w - 1][0];                                        \
            ezm1[1] = sEdgeR[ER][w - 1][1];                                        \
        }                                                                          \
        /* local H + J/E polynomial — overlaps poll RT */                          \
        float phi[NRMAX], jpart[NRMAX];                                            \
        _Pragma("unroll")                                                          \
        for (int r = 0; r < NRMAX; ++r) {                                          \
            hx[r]  = fHx[r]  * (hx[r]  - dbhx * (ezp1[r] - ez[r]));                \
            hxm[r] = fHxm[r] * (hxm[r] - dbhx * (ez[r] - ezm1[r]));                \
            float jp = ca * jz[r] + cb * jold[r] + cd * ez[r] + ce * eold[r];      \
            jpart[r] = jp;                                                         \
            phi[r]   = jp + jz[r];                                                 \
        }                                                                          \
        const unsigned seqv = want + 1u;                                           \
        if (nrows == 2) {                                                          \
            /* interior hy pre-poll */                                             \
            hy[0] = fHy[0] * (hy[0] + dbhy * (ez[1] - ez[0]));                     \
            /* wait bottom packet -> row 0 -> publish top */                       \
            if (nB) { while (__float_as_uint(vB.w) < want) vB = ld_pkt(pBr[PR]); } \
            float hyPrev = fHyHalo * (vB.y + dbhy * (ez[0] - vB.x));               \
            EUPD(0, hyPrev, s0);                                                   \
            st_pkt(pTw[PW], ez[0], 0.f, seqv);                                     \
            /* wait top packet -> row 1 -> publish bottom */                       \
            if (nT) { while (__float_as_uint(vT.w) < want) vT = ld_pkt(pTr[PR]); } \
            hy[1] = fHy[1] * (hy[1] + dbhy * (vT.x - ez[1]));                      \
            EUPD(1, hy[0], s1);                                                    \
            st_pkt(pBw[PW], ez[1], hy[1], seqv);                                   \
        } else {                                                                   \
            /* single row: needs both packets before its E update */               \
            if (nB) { while (__float_as_uint(vB.w) < want) vB = ld_pkt(pBr[PR]); } \
            float hyPrev = fHyHalo * (vB.y + dbhy * (ez[0] - vB.x));               \
            if (nT) { while (__float_as_uint(vT.w) < want) vT = ld_pkt(pTr[PR]); } \
            hy[0] = fHy[0] * (hy[0] + dbhy * (vT.x - ez[0]));                      \
            EUPD(0, hyPrev, s0);                                                   \
            st_pkt(pTw[PW], ez[0], 0.f, seqv);                                     \
            st_pkt(pBw[PW], ez[0], hy[0], seqv);                                   \
        }                                                                          \
        /* publish warp-edge Ez (state T+1) */                                     \
        if (lane == 0) {                                                           \
            sEdgeL[EW][w][0] = ez[0];                                              \
            sEdgeL[EW][w][1] = ez[1];                                              \
        }                                                                          \
        if (lane == 31) {                                                          \
            sEdgeR[EW][w][0] = ez[0];                                              \
            sEdgeR[EW][w][1] = ez[1];                                              \
        }                                                                          \
        __syncthreads();                                                           \
    } while (0)

    int t = 0;
    for (; t + 1 < n; t += 2) {
        STEP_BODY(t,     1, 0, 0, 1);
        STEP_BODY(t + 1, 0, 1, 1, 0);
    }
    if (t < n) {
        STEP_BODY(t, 1, 0, 0, 1);
    }
#undef STEP_BODY
#undef EUPD

    #pragma unroll
    for (int r = 0; r < NRMAX; ++r) {
        if (r < nrows && colE) out[(r0 + r) * TYDIM + j] = ez[r];
    }

    // Advance epoch for the next graph replay (same value from every block)
    if (j == 0) *(volatile unsigned*)&g_epoch = base + (unsigned)n;
}

extern "C" void kernel_launch(void* const* d_in, const int* in_sizes, int n_in,
                              void* d_out, int out_size) {
    const float* src    = (const float*)d_in[0];
    const float* C1a    = (const float*)d_in[1];
    const float* C2a    = (const float*)d_in[2];
    const float* Cbdxa  = (const float*)d_in[3];
    const float* Cbdya  = (const float*)d_in[4];
    const float* dbhxa  = (const float*)d_in[5];
    const float* dbhya  = (const float*)d_in[6];
    const float* Caa    = (const float*)d_in[7];
    const float* Cba    = (const float*)d_in[8];
    const float* Cca    = (const float*)d_in[9];
    const float* Cda    = (const float*)d_in[10];
    const float* Cea    = (const float*)d_in[11];
    const float* sigex  = (const float*)d_in[12];
    const float* sigey  = (const float*)d_in[13];
    const float* sighx  = (const float*)d_in[14];
    const float* sighy  = (const float*)d_in[15];
    const int*   nsp    = (n_in >= 17) ? (const int*)d_in[16] : nullptr;

    const double EPS0 = 1e-9 / 36.0 / M_PI;
    const double MU0  = 4.0 * M_PI * 1e-7;
    const double C0   = 1.0 / sqrt(MU0 * EPS0);
    const double DX = 2.5e-8, DY = 2.5e-8;
    const double DT = 0.99 / C0 / sqrt(1.0 / (DX * DX) + 1.0 / (DY * DY));
    const float kE  = (float)(DT / EPS0);
    const float kMu = (float)(DT / MU0);

    fdtd_mlor_kernel<<<NBLK, NT>>>(src, in_sizes[0],
                                   C1a, C2a, Cbdxa, Cbdya, dbhxa, dbhya,
                                   Caa, Cba, Cca, Cda, Cea,
                                   sigex, sigey, sighx, sighy,
                                   nsp, (float*)d_out, kE, kMu);
    (void)out_size;
}

// round 17
// speedup vs baseline: 1.1788x; 1.1788x over previous
#include <cuda_runtime.h>
#include <math.h>

#ifndef M_PI
#define M_PI 3.14159265358979323846
#endif

#define NBLK  148
#define NT    448
#define NWARP 14
#define TXDIM 421
#define TYDIM 421
#define NRMAX 3
#define SRCI  210
#define SRCJ  210
#define SRCBUF 256

// Flag+data packets, ring depth 2 (write slot t&1, read slot (t+1)&1):
//  pktT: {ez_row_first, 0, _, seq} — consumed by bid-1 as ezBot
//  pktB: {ez_row_last, hy_row_last, _, seq} — consumed by bid+1 as ezTop/hyTop
__device__ float4   g_pktT[2][NBLK][NT];
__device__ float4   g_pktB[2][NBLK][NT];
__device__ unsigned g_epoch;   // monotonic across graph replays

static __device__ __forceinline__ void st_pkt(float4* p, float x, float y, unsigned seq) {
    asm volatile("st.volatile.global.v4.f32 [%0], {%1,%2,%3,%4};"
                 :: "l"(p), "f"(x), "f"(y), "f"(0.f), "f"(__uint_as_float(seq)) : "memory");
}
static __device__ __forceinline__ float4 ld_pkt(const float4* p) {
    float4 v;
    asm volatile("ld.volatile.global.v4.f32 {%0,%1,%2,%3}, [%4];"
                 : "=f"(v.x), "=f"(v.y), "=f"(v.z), "=f"(v.w) : "l"(p) : "memory");
    return v;
}
// Pairwise named warp barrier (2 warps = 64 threads). Ids 1..13 (0 = __syncthreads).
#define NBAR(id) asm volatile("bar.sync %0, 64;" :: "r"(id) : "memory")

__global__ void __launch_bounds__(NT, 1)
fdtd_mlor_kernel(const float* __restrict__ src, int src_len,
                 const float* __restrict__ C1a, const float* __restrict__ C2a,
                 const float* __restrict__ Cbdxa, const float* __restrict__ Cbdya,
                 const float* __restrict__ dbhxa, const float* __restrict__ dbhya,
                 const float* __restrict__ Caa, const float* __restrict__ Cba,
                 const float* __restrict__ Cca, const float* __restrict__ Cda,
                 const float* __restrict__ Cea,
                 const float* __restrict__ sig_ex, const float* __restrict__ sig_ey,
                 const float* __restrict__ sig_hx, const float* __restrict__ sig_hy,
                 const int* __restrict__ nsp,
                 float* __restrict__ out,
                 float kE, float kMu)
{
    const int bid  = blockIdx.x;
    const int j    = threadIdx.x;
    const int w    = j >> 5;
    const int lane = j & 31;

    const float ca   = Caa[0], cb = Cba[0], cc = Cca[0], cd = Cda[0], ce = Cea[0];
    const float C1   = C1a[0], C2 = C2a[0];
    const float Cbdx = Cbdxa[0], Cbdy = Cbdya[0];
    const float dbhx = dbhxa[0], dbhy = dbhya[0];

    int n = nsp ? nsp[0] : 200;
    if (n > src_len) n = src_len;
    if (n < 0) n = 0;

    const int r0 = (bid * TXDIM) / NBLK;
    const int r1 = ((bid + 1) * TXDIM) / NBLK;
    const int nrows = r1 - r0;                 // 2 or 3 (block-uniform)
    const bool hasL = (bid > 0);
    const bool hasU = (bid < NBLK - 1);

    // Validity — folded into coefficients (zero => field stays 0: border mask).
    const bool colE = (j < TYDIM);
    const bool colH = (j < TYDIM - 1);
    const bool colM = (j >= 1 && j < TYDIM);
    const bool inJ  = (j >= 1 && j <= TYDIM - 2);

    float cEyE = 1.f, cEyMu = 1.f, cHyMu = 1.f, cHyMuM = 1.f;
    if (colE) { float s = sig_ey[j]; cEyE = expf(-s * kE); cEyMu = expf(-s * kMu); }
    if (colH) cHyMu  = expf(-sig_hy[j]     * kMu);
    if (colM) cHyMuM = expf(-sig_hy[j - 1] * kMu);

    float fDe[NRMAX], fHx[NRMAX], fHxm[NRMAX], fHy[NRMAX];
    #pragma unroll
    for (int r = 0; r < NRMAX; ++r) {
        fDe[r] = 0.f; fHx[r] = 0.f; fHxm[r] = 0.f; fHy[r] = 0.f;
        if (r < nrows) {
            int i = r0 + r;
            float sx  = sig_ex[i];
            float rMu = expf(-sx * kMu);
            bool  inI = (i >= 1 && i <= TXDIM - 2);
            fDe[r]  = (inI && inJ) ? expf(-sx * kE) * cEyE : 0.f;
            fHx[r]  = colH ? rMu * cHyMu  : 0.f;
            fHxm[r] = colM ? rMu * cHyMuM : 0.f;
            fHy[r]  = (i < TXDIM - 1 && colE) ? expf(-sig_hx[i] * kMu) * cEyMu : 0.f;
        }
    }
    const float fHyHalo = (r0 > 0 && colE) ? expf(-sig_hx[r0 - 1] * kMu) * cEyMu : 0.f;

    // Field state — registers for the whole run
    float ez[NRMAX]   = {0.f, 0.f, 0.f};
    float eold[NRMAX] = {0.f, 0.f, 0.f};
    float jz[NRMAX]   = {0.f, 0.f, 0.f};
    float jold[NRMAX] = {0.f, 0.f, 0.f};
    float hx[NRMAX]   = {0.f, 0.f, 0.f};
    float hxm[NRMAX]  = {0.f, 0.f, 0.f};
    float hy[NRMAX]   = {0.f, 0.f, 0.f};

    // Warp-edge Ez triples (float4, double-buffered). Protected by the PAIRWISE
    // barrier between the producing and consuming warps; never spun on.
    __shared__ float4 sEL[2][NWARP];   // lane0  column of each warp
    __shared__ float4 sER[2][NWARP];   // lane31 column of each warp
    __shared__ float  sSrc[SRCBUF];

    if (j < 2 * NWARP) { ((float4*)sEL)[j] = make_float4(0.f, 0.f, 0.f, 0.f);
                         ((float4*)sER)[j] = make_float4(0.f, 0.f, 0.f, 0.f); }
    if (j < n && j < SRCBUF) sSrc[j] = src[j];

    const unsigned base = *(volatile unsigned*)&g_epoch;

    // Loop-invariant packet pointers (slots compile-time per unrolled body)
    const int bidm = hasL ? bid - 1 : bid;
    const int bidp = hasU ? bid + 1 : bid;
    const float4* pBr[2] = { &g_pktB[0][bidm][j], &g_pktB[1][bidm][j] };
    const float4* pTr[2] = { &g_pktT[0][bidp][j], &g_pktT[1][bidp][j] };
    float4*       pTw[2] = { &g_pktT[0][bid][j],  &g_pktT[1][bid][j]  };
    float4*       pBw[2] = { &g_pktB[0][bid][j],  &g_pktB[1][bid][j]  };

    const bool srcBlk = (r0 <= SRCI) && (SRCI < r1) && (j == SRCJ);
    const bool s0 = srcBlk && (SRCI - r0 == 0);
    const bool s1 = srcBlk && (SRCI - r0 == 1);
    const bool s2 = srcBlk && (SRCI - r0 == 2);

    const bool hasWL = (w > 0);
    const bool hasWR = (w < NWARP - 1);

    __syncthreads();   // init visible to ALL warps (barrier id 0, once)

#define EUPD(r, hyBelow, sflag)                                                    \
    do {                                                                           \
        float chy_ = hy[(r)] - (hyBelow);                                          \
        float chx_ = hx[(r)] - hxm[(r)];                                           \
        float ezn_ = fDe[(r)] * (C1 * ez[(r)] + Cbdx * chy_ - Cbdy * chx_          \
                                 - C2 * phi[(r)]);                                 \
        if (sflag) ezn_ += sv;                                                     \
        jold[(r)] = jz[(r)]; jz[(r)] = jpart[(r)] + cc * ezn_;                     \
        eold[(r)] = ez[(r)]; ez[(r)] = ezn_;                                       \
    } while (0)

    // One full step. PR/PW = packet read/write slot, ER/EW = edge read/write slot.
#define STEP_BODY(T, PR, PW, ER, EW)                                               \
    do {                                                                           \
        const unsigned want = base + (unsigned)(T);                                \
        const bool nB = ((T) > 0) && hasL;                                         \
        const bool nT = ((T) > 0) && hasU;                                         \
        float4 vB = make_float4(0.f, 0.f, 0.f, 0.f);                               \
        float4 vT = make_float4(0.f, 0.f, 0.f, 0.f);                               \
        if (nB) vB = ld_pkt(pBr[PR]);                                              \
        if (nT) vT = ld_pkt(pTr[PR]);                                              \
        const float sv = sSrc[(T)];                                                \
        /* j±1 exchange: shfl in-warp, shared float4 at warp edges */              \
        float ezp1[NRMAX], ezm1[NRMAX];                                            \
        _Pragma("unroll")                                                          \
        for (int r = 0; r < NRMAX; ++r) {                                          \
            ezp1[r] = __shfl_down_sync(0xffffffffu, ez[r], 1);                     \
            ezm1[r] = __shfl_up_sync  (0xffffffffu, ez[r], 1);                     \
        }                                                                          \
        if (lane == 31 && hasWR) {                                                 \
            float4 e = sEL[ER][w + 1];                                             \
            ezp1[0] = e.x; ezp1[1] = e.y; ezp1[2] = e.z;                           \
        }                                                                          \
        if (lane == 0 && hasWL) {                                                  \
            float4 e = sER[ER][w - 1];                                             \
            ezm1[0] = e.x; ezm1[1] = e.y; ezm1[2] = e.z;                           \
        }                                                                          \
        /* local H + J/E polynomial — overlaps poll RT */                          \
        float phi[NRMAX], jpart[NRMAX];                                            \
        _Pragma("unroll")                                                          \
        for (int r = 0; r < NRMAX; ++r) {                                          \
            hx[r]  = fHx[r]  * (hx[r]  - dbhx * (ezp1[r] - ez[r]));                \
            hxm[r] = fHxm[r] * (hxm[r] - dbhx * (ez[r] - ezm1[r]));                \
            float jp = ca * jz[r] + cb * jold[r] + cd * ez[r] + ce * eold[r];      \
            jpart[r] = jp;                                                         \
            phi[r]   = jp + jz[r];                                                 \
        }                                                                          \
        hy[0] = fHy[0] * (hy[0] + dbhy * (ez[1] - ez[0]));                         \
        if (nrows == 3) {                                                          \
            hy[1] = fHy[1] * (hy[1] + dbhy * (ez[2] - ez[1]));                     \
            EUPD(1, hy[0], s1);      /* interior row in the poll shadow */         \
        }                                                                          \
        /* wait bottom packet -> row 0 -> publish top */                           \
        if (nB) { while (__float_as_uint(vB.w) < want) vB = ld_pkt(pBr[PR]); }     \
        const float hyPrev = fHyHalo * (vB.y + dbhy * (ez[0] - vB.x));             \
        const unsigned seqv = want + 1u;                                           \
        EUPD(0, hyPrev, s0);                                                       \
        st_pkt(pTw[PW], ez[0], 0.f, seqv);                                         \
        /* wait top packet -> last row -> publish bottom */                        \
        if (nT) { while (__float_as_uint(vT.w) < want) vT = ld_pkt(pTr[PR]); }     \
        if (nrows == 3) {                                                          \
            hy[2] = fHy[2] * (hy[2] + dbhy * (vT.x - ez[2]));                      \
            EUPD(2, hy[1], s2);                                                    \
            st_pkt(pBw[PW], ez[2], hy[2], seqv);                                   \
        } else {                                                                   \
            hy[1] = fHy[1] * (hy[1] + dbhy * (vT.x - ez[1]));                      \
            EUPD(1, hy[0], s1);                                                    \
            st_pkt(pBw[PW], ez[1], hy[1], seqv);                                   \
        }                                                                          \
        /* publish warp-edge Ez (state T+1) */                                     \
        if (lane == 0)  sEL[EW][w] = make_float4(ez[0], ez[1], ez[2], 0.f);        \
        if (lane == 31) sER[EW][w] = make_float4(ez[0], ez[1], ez[2], 0.f);        \
        /* PAIRWISE warp barriers: sync with left pair (id w), then right pair    */\
        /* (id w+1). Linear left-to-right resolution — acyclic, no deadlock.      */\
        /* bar.sync drains STS, ordering the sEdge publishes for both neighbors. */\
        if (hasWL) NBAR(w);                                                        \
        if (hasWR) NBAR(w + 1);                                                    \
    } while (0)

    int t = 0;
    for (; t + 1 < n; t += 2) {
        STEP_BODY(t,     1, 0, 0, 1);
        STEP_BODY(t + 1, 0, 1, 1, 0);
    }
    if (t < n) {
        STEP_BODY(t, 1, 0, 0, 1);
    }
#undef STEP_BODY
#undef EUPD

    #pragma unroll
    for (int r = 0; r < NRMAX; ++r) {
        if (r < nrows && colE) out[(r0 + r) * TYDIM + j] = ez[r];
    }

    // Advance epoch for the next graph replay (same value from every block)
    if (j == 0) *(volatile unsigned*)&g_epoch = base + (unsigned)n;
}

extern "C" void kernel_launch(void* const* d_in, const int* in_sizes, int n_in,
                              void* d_out, int out_size) {
    const float* src    = (const float*)d_in[0];
    const float* C1a    = (const float*)d_in[1];
    const float* C2a    = (const float*)d_in[2];
    const float* Cbdxa  = (const float*)d_in[3];
    const float* Cbdya  = (const float*)d_in[4];
    const float* dbhxa  = (const float*)d_in[5];
    const float* dbhya  = (const float*)d_in[6];
    const float* Caa    = (const float*)d_in[7];
    const float* Cba    = (const float*)d_in[8];
    const float* Cca    = (const float*)d_in[9];
    const float* Cda    = (const float*)d_in[10];
    const float* Cea    = (const float*)d_in[11];
    const float* sigex  = (const float*)d_in[12];
    const float* sigey  = (const float*)d_in[13];
    const float* sighx  = (const float*)d_in[14];
    const float* sighy  = (const float*)d_in[15];
    const int*   nsp    = (n_in >= 17) ? (const int*)d_in[16] : nullptr;

    const double EPS0 = 1e-9 / 36.0 / M_PI;
    const double MU0  = 4.0 * M_PI * 1e-7;
    const double C0   = 1.0 / sqrt(MU0 * EPS0);
    const double DX = 2.5e-8, DY = 2.5e-8;
    const double DT = 0.99 / C0 / sqrt(1.0 / (DX * DX) + 1.0 / (DY * DY));
    const float kE  = (float)(DT / EPS0);
    const float kMu = (float)(DT / MU0);

    fdtd_mlor_kernel<<<NBLK, NT>>>(src, in_sizes[0],
                                   C1a, C2a, Cbdxa, Cbdya, dbhxa, dbhya,
                                   Caa, Cba, Cca, Cda, Cea,
                                   sigex, sigey, sighx, sighy,
                                   nsp, (float*)d_out, kE, kMu);
    (void)out_size;
}